// round 7
// baseline (speedup 1.0000x reference)
#include <cuda_runtime.h>
#include <cuda_bf16.h>
#include <cstdint>

// Problem constants
#define NN 100000
#define EE 1600000
#define HH 4
#define DD 32
#define EFF 32
#define ET 8
#define HD 128           // H*D
#define NEG_SLOPE 0.2f

#define SCAN_BLK 1024
#define SCAN_NB  ((NN + SCAN_BLK - 1) / SCAN_BLK)   // 98

// Scratch (static device allocations — allowed)
__device__ __nv_bfloat16 g_fsh[NN * HD];  // feat*fc in bf16   (25.6 MB)
__device__ float g_el[NN * HH];        // left attention logits
__device__ float g_er[NN * HH];        // right attention logits
__device__ float g_s [NN * HH];        // softmax denominators
__device__ float g_ee[ET * HH];        // per-edge-type scores
__device__ int   g_deg[NN];            // dst degree histogram
__device__ int   g_rowptr[NN + 1];     // CSR row pointers
__device__ int   g_cursor[NN];         // scatter cursors
__device__ int   g_bsum[SCAN_NB];      // per-block scan totals
__device__ int   g_boff[SCAN_NB];      // per-block exclusive offsets
__device__ int4  g_rec[EE];            // {src, a01_bf16, a23_bf16, pad}, dst-sorted (25.6 MB)

// ---------------------------------------------------------------------------
// Kernel 0: edge-type scores + zero deg (deg must be zero before k_node's
//           fused histogram).
// ---------------------------------------------------------------------------
__global__ void k_init(const float* __restrict__ edge_emb,
                       const float* __restrict__ W_e,
                       const float* __restrict__ attn_e) {
    int gtid = blockIdx.x * blockDim.x + threadIdx.x;
    if (blockIdx.x == 0 && threadIdx.x < ET * HH) {
        int et = threadIdx.x >> 2;
        int h  = threadIdx.x & 3;
        float acc = 0.f;
        for (int f = 0; f < EFF; f++) {
            const float* w = W_e + (h * EFF + f) * EFF;
            float emb = 0.f;
            #pragma unroll
            for (int g = 0; g < EFF; g++)
                emb += edge_emb[et * EFF + g] * w[g];
            acc += attn_e[h * EFF + f] * emb;
        }
        g_ee[et * HH + h] = acc;
    }
    for (int i = gtid; i < NN; i += gridDim.x * blockDim.x)
        g_deg[i] = 0;
}

// ---------------------------------------------------------------------------
// Kernel 1: per-node (warp per node) + fused dst-degree histogram.
//   fs fp32 math, bf16 store. Zeroes g_s (consumed by k_score next).
// ---------------------------------------------------------------------------
__global__ void k_node(const float* __restrict__ feat,
                       const float* __restrict__ fc,
                       const float* __restrict__ attn_l,
                       const float* __restrict__ attn_r,
                       const int*   __restrict__ node_types,
                       const int*   __restrict__ dst) {
    int gtid = blockIdx.x * blockDim.x + threadIdx.x;
    int warp = gtid >> 5;
    int lane = threadIdx.x & 31;

    // fused degree histogram: one edge per thread (3.2M threads >= EE)
    if (gtid < EE)
        atomicAdd(&g_deg[dst[gtid]], 1);

    if (warp >= NN) return;

    int nt = node_types[warp];
    float4 f  = __ldcs((const float4*)(feat + (size_t)warp * HD) + lane);
    float4 c  = ((const float4*)(fc   + nt * HD))[lane];
    float4 fs = make_float4(f.x * c.x, f.y * c.y, f.z * c.z, f.w * c.w);

    __nv_bfloat162 lo = __floats2bfloat162_rn(fs.x, fs.y);
    __nv_bfloat162 hi = __floats2bfloat162_rn(fs.z, fs.w);
    uint2 packed;
    packed.x = *reinterpret_cast<unsigned int*>(&lo);
    packed.y = *reinterpret_cast<unsigned int*>(&hi);
    ((uint2*)(g_fsh + (size_t)warp * HD))[lane] = packed;

    float4 al = ((const float4*)attn_l)[lane];
    float4 ar = ((const float4*)attn_r)[lane];
    float el = fs.x * al.x + fs.y * al.y + fs.z * al.z + fs.w * al.w;
    float er = fs.x * ar.x + fs.y * ar.y + fs.z * ar.z + fs.w * ar.w;

    #pragma unroll
    for (int off = 4; off >= 1; off >>= 1) {
        el += __shfl_down_sync(0xffffffffu, el, off);
        er += __shfl_down_sync(0xffffffffu, er, off);
    }
    int h = lane >> 3;
    if ((lane & 7) == 0) {
        g_el[warp * HH + h] = el;
        g_er[warp * HH + h] = er;
    }
    if (lane < HH) g_s[warp * HH + lane] = 0.f;
}

// ---------------------------------------------------------------------------
// Helper: compute exp scores for one edge (used identically in k_score and
// k_scatter -> bitwise-identical results, deterministic).
// ---------------------------------------------------------------------------
__device__ __forceinline__ float4 edge_ex(int s, int d, int t) {
    float4 el = ((const float4*)g_el)[s];
    float4 er = ((const float4*)g_er)[d];
    float4 ee = ((const float4*)g_ee)[t];
    float v0 = el.x + er.x + ee.x;
    float v1 = el.y + er.y + ee.y;
    float v2 = el.z + er.z + ee.z;
    float v3 = el.w + er.w + ee.w;
    v0 = v0 > 0.f ? v0 : NEG_SLOPE * v0;
    v1 = v1 > 0.f ? v1 : NEG_SLOPE * v1;
    v2 = v2 > 0.f ? v2 : NEG_SLOPE * v2;
    v3 = v3 > 0.f ? v3 : NEG_SLOPE * v3;
    return make_float4(__expf(v0), __expf(v1), __expf(v2), __expf(v3));
}

// ---------------------------------------------------------------------------
// Kernel 2: per-edge softmax-denominator reduction. One thread per edge.
//   No stores — ex is recomputed in k_scatter.
// ---------------------------------------------------------------------------
__global__ void k_score(const int* __restrict__ src,
                        const int* __restrict__ dst,
                        const int* __restrict__ e_feat) {
    int e = blockIdx.x * blockDim.x + threadIdx.x;
    if (e >= EE) return;
    int d = dst[e];
    float4 ex = edge_ex(src[e], d, e_feat[e]);

    float* sp = g_s + d * HH;
    asm volatile("red.global.add.v4.f32 [%0], {%1, %2, %3, %4};"
                 :: "l"(sp), "f"(ex.x), "f"(ex.y), "f"(ex.z), "f"(ex.w)
                 : "memory");
}

// ---------------------------------------------------------------------------
// Kernel 3a: per-block exclusive scan of g_deg.
// ---------------------------------------------------------------------------
__global__ void k_scan_local() {
    __shared__ int warp_sums[32];
    int tid = threadIdx.x, lane = tid & 31, wid = tid >> 5;
    int i = blockIdx.x * SCAN_BLK + tid;
    int v = (i < NN) ? g_deg[i] : 0;
    int x = v;
    #pragma unroll
    for (int off = 1; off < 32; off <<= 1) {
        int y = __shfl_up_sync(0xffffffffu, x, off);
        if (lane >= off) x += y;
    }
    if (lane == 31) warp_sums[wid] = x;
    __syncthreads();
    if (wid == 0) {
        int w = warp_sums[lane];
        #pragma unroll
        for (int off = 1; off < 32; off <<= 1) {
            int y = __shfl_up_sync(0xffffffffu, w, off);
            if (lane >= off) w += y;
        }
        warp_sums[lane] = w;
    }
    __syncthreads();
    int excl = (wid ? warp_sums[wid - 1] : 0) + x - v;
    if (i < NN) g_rowptr[i] = excl;
    if (tid == SCAN_BLK - 1) g_bsum[blockIdx.x] = excl + v;
}

// ---------------------------------------------------------------------------
// Kernel 3b: scan the block totals.
// ---------------------------------------------------------------------------
__global__ void k_scan_bsum() {
    __shared__ int warp_sums[4];
    int tid = threadIdx.x, lane = tid & 31, wid = tid >> 5;   // 128 threads
    int v = (tid < SCAN_NB) ? g_bsum[tid] : 0;
    int x = v;
    #pragma unroll
    for (int off = 1; off < 32; off <<= 1) {
        int y = __shfl_up_sync(0xffffffffu, x, off);
        if (lane >= off) x += y;
    }
    if (lane == 31) warp_sums[wid] = x;
    __syncthreads();
    int carry = 0;
    for (int w = 0; w < wid; w++) carry += warp_sums[w];
    if (tid < SCAN_NB) g_boff[tid] = carry + x - v;
    if (tid == SCAN_NB - 1) g_rowptr[NN] = carry + x;
}

// ---------------------------------------------------------------------------
// Kernel 3c: add block offsets; init cursors.
// ---------------------------------------------------------------------------
__global__ void k_scan_add() {
    int i = blockIdx.x * SCAN_BLK + threadIdx.x;
    if (i >= NN) return;
    int r = g_rowptr[i] + g_boff[blockIdx.x];
    g_rowptr[i] = r;
    g_cursor[i] = r;
}

// ---------------------------------------------------------------------------
// Kernel 4: scatter. One thread per edge.
//   Recomputes ex (identical FP sequence as k_score), a = ex/s.
//   a-output coalesced fp32 (exact); sorted record one 16B store.
// ---------------------------------------------------------------------------
__global__ void k_scatter(const int* __restrict__ src,
                          const int* __restrict__ dst,
                          const int* __restrict__ e_feat,
                          float* __restrict__ out) {
    int e = blockIdx.x * blockDim.x + threadIdx.x;
    if (e >= EE) return;
    int s = src[e], d = dst[e];

    float4 ex = edge_ex(s, d, e_feat[e]);
    float4 sv = ((const float4*)g_s)[d];
    float4 a  = make_float4(ex.x / sv.x, ex.y / sv.y, ex.z / sv.z, ex.w / sv.w);

    __stcs((float4*)(out + (size_t)NN * HD) + e, a);   // a output, coalesced fp32

    __nv_bfloat162 alo = __floats2bfloat162_rn(a.x, a.y);
    __nv_bfloat162 ahi = __floats2bfloat162_rn(a.z, a.w);
    int4 rec;
    rec.x = s;
    rec.y = *reinterpret_cast<int*>(&alo);
    rec.z = *reinterpret_cast<int*>(&ahi);
    rec.w = 0;

    int pos = atomicAdd(&g_cursor[d], 1);
    __stcs(&g_rec[pos], rec);
}

// ---------------------------------------------------------------------------
// Kernel 5: gather-side aggregation. One warp per dst node; atomic-free.
// ---------------------------------------------------------------------------
__global__ void __launch_bounds__(256) k_agg(const float* __restrict__ feat,
                                             float* __restrict__ out) {
    int warp = (blockIdx.x * blockDim.x + threadIdx.x) >> 5;
    int lane = threadIdx.x & 31;
    if (warp >= NN) return;

    int beg = g_rowptr[warp];
    int end = g_rowptr[warp + 1];
    int h = lane >> 3;
    bool hiHalf = (h & 1);
    bool hiWord = (h >> 1);

    float accx = 0.f, accy = 0.f, accz = 0.f, accw = 0.f;
    #pragma unroll 8
    for (int j = beg; j < end; j++) {
        int4 rec = __ldcs(&g_rec[j]);
        int  s   = rec.x;
        int  aw  = hiWord ? rec.z : rec.y;
        __nv_bfloat162 ap = *reinterpret_cast<__nv_bfloat162*>(&aw);
        float a = hiHalf ? __high2float(ap) : __low2float(ap);

        uint2 p = __ldg((const uint2*)(g_fsh + (size_t)s * HD) + lane);
        __nv_bfloat162 lo = *reinterpret_cast<__nv_bfloat162*>(&p.x);
        __nv_bfloat162 hi = *reinterpret_cast<__nv_bfloat162*>(&p.y);
        float2 flo = __bfloat1622float2(lo);
        float2 fhi = __bfloat1622float2(hi);
        accx += flo.x * a;
        accy += flo.y * a;
        accz += fhi.x * a;
        accw += fhi.y * a;
    }

    float4 f = __ldcs((const float4*)(feat + (size_t)warp * HD) + lane);
    float4 r = make_float4(f.x + accx, f.y + accy, f.z + accz, f.w + accw);
    __stcs((float4*)(out + (size_t)warp * HD) + lane, r);
}

// ---------------------------------------------------------------------------
extern "C" void kernel_launch(void* const* d_in, const int* in_sizes, int n_in,
                              void* d_out, int out_size) {
    const float* feat       = (const float*)d_in[0];
    const float* fc         = (const float*)d_in[1];
    const float* edge_emb   = (const float*)d_in[2];
    const float* W_e        = (const float*)d_in[3];
    const float* attn_l     = (const float*)d_in[4];
    const float* attn_r     = (const float*)d_in[5];
    const float* attn_e     = (const float*)d_in[6];
    const int*   node_types = (const int*)d_in[7];
    const int*   e_feat     = (const int*)d_in[8];
    const int*   src        = (const int*)d_in[9];
    const int*   dst        = (const int*)d_in[10];
    float* out = (float*)d_out;

    k_init<<<148, 256>>>(edge_emb, W_e, attn_e);

    int node_blocks = (NN + 7) / 8;            // warp per node; covers EE for histogram
    k_node<<<node_blocks, 256>>>(feat, fc, attn_l, attn_r, node_types, dst);

    int edge_blocks = (EE + 255) / 256;
    k_score<<<edge_blocks, 256>>>(src, dst, e_feat);

    k_scan_local<<<SCAN_NB, SCAN_BLK>>>();
    k_scan_bsum<<<1, 128>>>();
    k_scan_add<<<SCAN_NB, SCAN_BLK>>>();

    k_scatter<<<edge_blocks, 256>>>(src, dst, e_feat, out);

    int agg_blocks = (NN + 7) / 8;             // warp per dst node
    k_agg<<<agg_blocks, 256>>>(feat, out);
}

// round 8
// speedup vs baseline: 1.0707x; 1.0707x over previous
#include <cuda_runtime.h>
#include <cuda_bf16.h>
#include <cstdint>

// Problem constants
#define NN 100000
#define EE 1600000
#define HH 4
#define DD 32
#define EFF 32
#define ET 8
#define HD 128           // H*D
#define NEG_SLOPE 0.2f

#define SCAN_BLK 1024
#define SCAN_NB  ((NN + SCAN_BLK - 1) / SCAN_BLK)   // 98

// Scratch (static device allocations — allowed)
__device__ __nv_bfloat16 g_fsh[NN * HD];  // feat*fc in bf16   (25.6 MB)
__device__ float g_ex[EE * HH];        // exp(leaky_relu(score)) (25.6 MB)
__device__ float g_el[NN * HH];        // left attention logits
__device__ float g_er[NN * HH];        // right attention logits
__device__ float g_s [NN * HH];        // softmax denominators
__device__ float g_ee[ET * HH];        // per-edge-type scores
__device__ int   g_deg[NN];            // dst degree histogram
__device__ int   g_rowptr[NN + 1];     // CSR row pointers
__device__ int   g_cursor[NN];         // scatter cursors
__device__ int   g_bsum[SCAN_NB];      // per-block scan totals
__device__ int   g_boff[SCAN_NB];      // per-block exclusive offsets
__device__ int4  g_rec[EE];            // {src, a01_bf16, a23_bf16, pad}, dst-sorted (25.6 MB)

// ---------------------------------------------------------------------------
// Kernel 0: edge-type embedding path.
// ---------------------------------------------------------------------------
__global__ void k_ee(const float* __restrict__ edge_emb,
                     const float* __restrict__ W_e,
                     const float* __restrict__ attn_e) {
    int t = threadIdx.x;
    if (t >= ET * HH) return;
    int et = t >> 2;
    int h  = t & 3;
    float acc = 0.f;
    for (int f = 0; f < EFF; f++) {
        const float* w = W_e + (h * EFF + f) * EFF;
        float emb = 0.f;
        #pragma unroll
        for (int g = 0; g < EFF; g++)
            emb += edge_emb[et * EFF + g] * w[g];
        acc += attn_e[h * EFF + f] * emb;
    }
    g_ee[et * HH + h] = acc;
}

// ---------------------------------------------------------------------------
// Kernel 1: per-node. One warp per node. fs fp32 math, bf16 store.
//   Also initializes out[node] = feat (residual) — feat is already in regs,
//   so k_agg never has to re-read feat.
// ---------------------------------------------------------------------------
__global__ void k_node(const float* __restrict__ feat,
                       const float* __restrict__ fc,
                       const float* __restrict__ attn_l,
                       const float* __restrict__ attn_r,
                       const int*   __restrict__ node_types,
                       float*       __restrict__ out) {
    int warp = (blockIdx.x * blockDim.x + threadIdx.x) >> 5;
    int lane = threadIdx.x & 31;
    if (warp >= NN) return;

    int nt = node_types[warp];
    float4 f  = __ldcs((const float4*)(feat + (size_t)warp * HD) + lane);
    float4 c  = ((const float4*)(fc   + nt * HD))[lane];
    float4 fs = make_float4(f.x * c.x, f.y * c.y, f.z * c.z, f.w * c.w);

    __stcs((float4*)(out + (size_t)warp * HD) + lane, f);   // residual init

    __nv_bfloat162 lo = __floats2bfloat162_rn(fs.x, fs.y);
    __nv_bfloat162 hi = __floats2bfloat162_rn(fs.z, fs.w);
    uint2 packed;
    packed.x = *reinterpret_cast<unsigned int*>(&lo);
    packed.y = *reinterpret_cast<unsigned int*>(&hi);
    ((uint2*)(g_fsh + (size_t)warp * HD))[lane] = packed;

    float4 al = ((const float4*)attn_l)[lane];
    float4 ar = ((const float4*)attn_r)[lane];
    float el = fs.x * al.x + fs.y * al.y + fs.z * al.z + fs.w * al.w;
    float er = fs.x * ar.x + fs.y * ar.y + fs.z * ar.z + fs.w * ar.w;

    #pragma unroll
    for (int off = 4; off >= 1; off >>= 1) {
        el += __shfl_down_sync(0xffffffffu, el, off);
        er += __shfl_down_sync(0xffffffffu, er, off);
    }
    int h = lane >> 3;
    if ((lane & 7) == 0) {
        g_el[warp * HH + h] = el;
        g_er[warp * HH + h] = er;
    }
    if (lane < HH) g_s[warp * HH + lane] = 0.f;
    if (lane == 4) g_deg[warp] = 0;
}

// ---------------------------------------------------------------------------
// Kernel 2: per-edge scores + dst histogram. One thread per edge.
// ---------------------------------------------------------------------------
__global__ void k_score(const int* __restrict__ src,
                        const int* __restrict__ dst,
                        const int* __restrict__ e_feat) {
    int e = blockIdx.x * blockDim.x + threadIdx.x;
    if (e >= EE) return;
    int s = src[e], d = dst[e], t = e_feat[e];

    float4 el = ((const float4*)g_el)[s];
    float4 er = ((const float4*)g_er)[d];
    float4 ee = ((const float4*)g_ee)[t];

    float v0 = el.x + er.x + ee.x;
    float v1 = el.y + er.y + ee.y;
    float v2 = el.z + er.z + ee.z;
    float v3 = el.w + er.w + ee.w;
    v0 = v0 > 0.f ? v0 : NEG_SLOPE * v0;
    v1 = v1 > 0.f ? v1 : NEG_SLOPE * v1;
    v2 = v2 > 0.f ? v2 : NEG_SLOPE * v2;
    v3 = v3 > 0.f ? v3 : NEG_SLOPE * v3;

    float4 ex = make_float4(__expf(v0), __expf(v1), __expf(v2), __expf(v3));
    __stcs((float4*)g_ex + e, ex);

    float* sp = g_s + d * HH;
    asm volatile("red.global.add.v4.f32 [%0], {%1, %2, %3, %4};"
                 :: "l"(sp), "f"(ex.x), "f"(ex.y), "f"(ex.z), "f"(ex.w)
                 : "memory");
    atomicAdd(&g_deg[d], 1);
}

// ---------------------------------------------------------------------------
// Kernel 3a: per-block exclusive scan of g_deg.
// ---------------------------------------------------------------------------
__global__ void k_scan_local() {
    __shared__ int warp_sums[32];
    int tid = threadIdx.x, lane = tid & 31, wid = tid >> 5;
    int i = blockIdx.x * SCAN_BLK + tid;
    int v = (i < NN) ? g_deg[i] : 0;
    int x = v;
    #pragma unroll
    for (int off = 1; off < 32; off <<= 1) {
        int y = __shfl_up_sync(0xffffffffu, x, off);
        if (lane >= off) x += y;
    }
    if (lane == 31) warp_sums[wid] = x;
    __syncthreads();
    if (wid == 0) {
        int w = warp_sums[lane];
        #pragma unroll
        for (int off = 1; off < 32; off <<= 1) {
            int y = __shfl_up_sync(0xffffffffu, w, off);
            if (lane >= off) w += y;
        }
        warp_sums[lane] = w;
    }
    __syncthreads();
    int excl = (wid ? warp_sums[wid - 1] : 0) + x - v;
    if (i < NN) g_rowptr[i] = excl;
    if (tid == SCAN_BLK - 1) g_bsum[blockIdx.x] = excl + v;
}

// ---------------------------------------------------------------------------
// Kernel 3b: scan the block totals.
// ---------------------------------------------------------------------------
__global__ void k_scan_bsum() {
    __shared__ int warp_sums[4];
    int tid = threadIdx.x, lane = tid & 31, wid = tid >> 5;   // 128 threads
    int v = (tid < SCAN_NB) ? g_bsum[tid] : 0;
    int x = v;
    #pragma unroll
    for (int off = 1; off < 32; off <<= 1) {
        int y = __shfl_up_sync(0xffffffffu, x, off);
        if (lane >= off) x += y;
    }
    if (lane == 31) warp_sums[wid] = x;
    __syncthreads();
    int carry = 0;
    for (int w = 0; w < wid; w++) carry += warp_sums[w];
    if (tid < SCAN_NB) g_boff[tid] = carry + x - v;
    if (tid == SCAN_NB - 1) g_rowptr[NN] = carry + x;
}

// ---------------------------------------------------------------------------
// Kernel 3c: add block offsets; init cursors.
// ---------------------------------------------------------------------------
__global__ void k_scan_add() {
    int i = blockIdx.x * SCAN_BLK + threadIdx.x;
    if (i >= NN) return;
    int r = g_rowptr[i] + g_boff[blockIdx.x];
    g_rowptr[i] = r;
    g_cursor[i] = r;
}

// ---------------------------------------------------------------------------
// Kernel 4: scatter. One thread per edge.
//   a computed fp32; a-output written coalesced fp32 (exact);
//   sorted record = one 16B store: {src, a as 4xbf16, pad}.
// ---------------------------------------------------------------------------
__global__ void k_scatter(const int* __restrict__ src,
                          const int* __restrict__ dst,
                          float* __restrict__ out) {
    int e = blockIdx.x * blockDim.x + threadIdx.x;
    if (e >= EE) return;
    int s = src[e], d = dst[e];

    float4 ex = __ldcs((const float4*)g_ex + e);
    float4 sv = ((const float4*)g_s)[d];
    float4 a  = make_float4(ex.x / sv.x, ex.y / sv.y, ex.z / sv.z, ex.w / sv.w);

    __stcs((float4*)(out + (size_t)NN * HD) + e, a);   // a output, coalesced fp32

    __nv_bfloat162 alo = __floats2bfloat162_rn(a.x, a.y);
    __nv_bfloat162 ahi = __floats2bfloat162_rn(a.z, a.w);
    int4 rec;
    rec.x = s;
    rec.y = *reinterpret_cast<int*>(&alo);
    rec.z = *reinterpret_cast<int*>(&ahi);
    rec.w = 0;

    int pos = atomicAdd(&g_cursor[d], 1);
    __stcs(&g_rec[pos], rec);
}

// ---------------------------------------------------------------------------
// Kernel 5: gather-side aggregation. One warp per dst node; no feat re-read.
//   msg accumulated in registers, then red.global.add.v4 into out (which
//   k_node pre-initialized with feat). Addresses are warp-private -> no
//   contention, REDG ~ store cost.
// ---------------------------------------------------------------------------
__global__ void __launch_bounds__(256) k_agg(float* __restrict__ out) {
    int warp = (blockIdx.x * blockDim.x + threadIdx.x) >> 5;
    int lane = threadIdx.x & 31;
    if (warp >= NN) return;

    int beg = g_rowptr[warp];
    int end = g_rowptr[warp + 1];
    int h = lane >> 3;
    bool hiHalf = (h & 1);     // which bf16 in the pair
    bool hiWord = (h >> 1);    // rec.y (heads 0,1) or rec.z (heads 2,3)

    float accx = 0.f, accy = 0.f, accz = 0.f, accw = 0.f;
    #pragma unroll 4
    for (int j = beg; j < end; j++) {
        int4 rec = __ldcs(&g_rec[j]);
        int  s   = rec.x;
        int  aw  = hiWord ? rec.z : rec.y;
        __nv_bfloat162 ap = *reinterpret_cast<__nv_bfloat162*>(&aw);
        float a = hiHalf ? __high2float(ap) : __low2float(ap);

        uint2 p = __ldg((const uint2*)(g_fsh + (size_t)s * HD) + lane);
        __nv_bfloat162 lo = *reinterpret_cast<__nv_bfloat162*>(&p.x);
        __nv_bfloat162 hi = *reinterpret_cast<__nv_bfloat162*>(&p.y);
        float2 flo = __bfloat1622float2(lo);
        float2 fhi = __bfloat1622float2(hi);
        accx += flo.x * a;
        accy += flo.y * a;
        accz += fhi.x * a;
        accw += fhi.y * a;
    }

    float* op = out + (size_t)warp * HD + lane * 4;
    asm volatile("red.global.add.v4.f32 [%0], {%1, %2, %3, %4};"
                 :: "l"(op), "f"(accx), "f"(accy), "f"(accz), "f"(accw)
                 : "memory");
}

// ---------------------------------------------------------------------------
extern "C" void kernel_launch(void* const* d_in, const int* in_sizes, int n_in,
                              void* d_out, int out_size) {
    const float* feat       = (const float*)d_in[0];
    const float* fc         = (const float*)d_in[1];
    const float* edge_emb   = (const float*)d_in[2];
    const float* W_e        = (const float*)d_in[3];
    const float* attn_l     = (const float*)d_in[4];
    const float* attn_r     = (const float*)d_in[5];
    const float* attn_e     = (const float*)d_in[6];
    const int*   node_types = (const int*)d_in[7];
    const int*   e_feat     = (const int*)d_in[8];
    const int*   src        = (const int*)d_in[9];
    const int*   dst        = (const int*)d_in[10];
    float* out = (float*)d_out;

    k_ee<<<1, 32>>>(edge_emb, W_e, attn_e);

    int node_blocks = (NN + 7) / 8;            // warp per node
    k_node<<<node_blocks, 256>>>(feat, fc, attn_l, attn_r, node_types, out);

    int edge_blocks = (EE + 255) / 256;
    k_score<<<edge_blocks, 256>>>(src, dst, e_feat);

    k_scan_local<<<SCAN_NB, SCAN_BLK>>>();
    k_scan_bsum<<<1, 128>>>();
    k_scan_add<<<SCAN_NB, SCAN_BLK>>>();

    k_scatter<<<edge_blocks, 256>>>(src, dst, out);

    int agg_blocks = (NN + 7) / 8;             // warp per dst node
    k_agg<<<agg_blocks, 256>>>(out);
}